// round 11
// baseline (speedup 1.0000x reference)
#include <cuda_runtime.h>
#include <math.h>

#define BATCH 8
#define SEQ   2048
#define DIN   1024
#define DHEAD 128
#define NROWS (BATCH * SEQ)

typedef unsigned int  u32;
typedef unsigned short u16;

// ---------------------------------------------------------------------------
// split-bf16 global scratch
// ---------------------------------------------------------------------------
__device__ __align__(16) u16 g_Wh[3 * DIN * DHEAD];
__device__ __align__(16) u16 g_Wl[3 * DIN * DHEAD];
__device__ __align__(16) u16 g_Qh[NROWS * DHEAD];
__device__ __align__(16) u16 g_Ql[NROWS * DHEAD];
__device__ __align__(16) u16 g_Kh[NROWS * DHEAD];
__device__ __align__(16) u16 g_Kl[NROWS * DHEAD];
__device__ __align__(16) u16 g_Vh[NROWS * DHEAD];
__device__ __align__(16) u16 g_Vl[NROWS * DHEAD];

// ---------------------------------------------------------------------------
// helpers
// ---------------------------------------------------------------------------
__device__ __forceinline__ u32 cvt2(float lo, float hi) {  // bf16(lo)|bf16(hi)<<16
    u32 r; asm("cvt.rn.bf16x2.f32 %0, %1, %2;" : "=r"(r) : "f"(hi), "f"(lo));
    return r;
}
__device__ __forceinline__ float bflo(u32 v) { return __uint_as_float(v << 16); }
__device__ __forceinline__ float bfhi(u32 v) { return __uint_as_float(v & 0xffff0000u); }

__device__ __forceinline__ u32 s2u(const void* p) {
    u32 a;
    asm("{.reg .u64 t; cvta.to.shared.u64 t, %1; cvt.u32.u64 %0, t;}" : "=r"(a) : "l"(p));
    return a;
}
__device__ __forceinline__ void cp16(u32 smem, const void* g) {
    asm volatile("cp.async.cg.shared.global [%0], [%1], 16;" :: "r"(smem), "l"(g));
}
#define CP_COMMIT() asm volatile("cp.async.commit_group;")
#define CP_WAIT0()  asm volatile("cp.async.wait_group 0;")

__device__ __forceinline__ void ldm_x4(u32& r0, u32& r1, u32& r2, u32& r3, u32 a) {
    asm volatile("ldmatrix.sync.aligned.m8n8.x4.shared.b16 {%0,%1,%2,%3},[%4];"
                 : "=r"(r0), "=r"(r1), "=r"(r2), "=r"(r3) : "r"(a));
}
__device__ __forceinline__ void ldm_x4t(u32& r0, u32& r1, u32& r2, u32& r3, u32 a) {
    asm volatile("ldmatrix.sync.aligned.m8n8.x4.trans.shared.b16 {%0,%1,%2,%3},[%4];"
                 : "=r"(r0), "=r"(r1), "=r"(r2), "=r"(r3) : "r"(a));
}
__device__ __forceinline__ void mma16816(float c[4], u32 a0, u32 a1, u32 a2, u32 a3,
                                         u32 b0, u32 b1) {
    asm volatile(
        "mma.sync.aligned.m16n8k16.row.col.f32.bf16.bf16.f32 "
        "{%0,%1,%2,%3},{%4,%5,%6,%7},{%8,%9},{%0,%1,%2,%3};"
        : "+f"(c[0]), "+f"(c[1]), "+f"(c[2]), "+f"(c[3])
        : "r"(a0), "r"(a1), "r"(a2), "r"(a3), "r"(b0), "r"(b1));
}

// ---------------------------------------------------------------------------
// split pass for W only (X is converted in-kernel by proj)
// ---------------------------------------------------------------------------
__global__ void split_w_kernel(const float* __restrict__ Wq,
                               const float* __restrict__ Wk,
                               const float* __restrict__ Wv)
{
    const int per = DIN * DHEAD / 4;
    int i = blockIdx.x * blockDim.x + threadIdx.x;
    if (i >= 3 * per) return;
    const float* src = (i < per) ? Wq : (i < 2 * per) ? Wk : Wv;
    float4 v = ((const float4*)src)[i % per];
    u32 h0 = cvt2(v.x, v.y), h1 = cvt2(v.z, v.w);
    u32 l0 = cvt2(v.x - bflo(h0), v.y - bfhi(h0));
    u32 l1 = cvt2(v.z - bflo(h1), v.w - bfhi(h1));
    ((uint2*)g_Wh)[i] = make_uint2(h0, h1);
    ((uint2*)g_Wl)[i] = make_uint2(l0, l1);
}

// ---------------------------------------------------------------------------
// Projection GEMM (exact round-8 code — proven 246.3us config).
// ---------------------------------------------------------------------------
#define PX_STR 40
#define PW_STR 136
#define PX_ELE (128 * PX_STR)
#define PW_ELE (32 * PW_STR)
#define PROJ_SMEM ((4 * PX_ELE + 4 * PW_ELE) * 2)   // 75776 B

__global__ __launch_bounds__(128) void proj_mma_kernel(
    const float* __restrict__ X,
    const float* __restrict__ bq, const float* __restrict__ bk,
    const float* __restrict__ bv)
{
    extern __shared__ __align__(16) u16 psm[];
    u16* Xh[2] = { psm,              psm + 2 * PX_ELE };
    u16* Xl[2] = { psm + PX_ELE,     psm + 3 * PX_ELE };
    u16* Wh[2] = { psm + 4 * PX_ELE,              psm + 4 * PX_ELE + 2 * PW_ELE };
    u16* Wl[2] = { psm + 4 * PX_ELE + PW_ELE,     psm + 4 * PX_ELE + 3 * PW_ELE };

    const int tid = threadIdx.x, lane = tid & 31, wid = tid >> 5;
    const int sel = blockIdx.x;
    const u16* gWh = g_Wh + sel * (DIN * DHEAD);
    const u16* gWl = g_Wl + sel * (DIN * DHEAD);
    const float* bias = (sel == 0) ? bq : (sel == 1) ? bk : bv;
    u16* outh = (sel == 0) ? g_Qh : (sel == 1) ? g_Kh : g_Vh;
    u16* outl = (sel == 0) ? g_Ql : (sel == 1) ? g_Kl : g_Vl;

    float c[2][16][4];
    #pragma unroll
    for (int mh = 0; mh < 2; mh++)
        #pragma unroll
        for (int i = 0; i < 16; i++)
            #pragma unroll
            for (int j = 0; j < 4; j++) c[mh][i][j] = 0.f;

    const size_t xrow0 = (size_t)blockIdx.y * 128;
    const int xr = tid >> 3, xc = (tid & 7) * 4;
    const int wr0 = tid >> 4, wc0 = (tid & 15) * 8;
    const u32 a_off0 = (u32)(wid * 32 + (lane & 15)) * (PX_STR * 2) +
                       ((lane & 16) ? 16u : 0u);
    const u32 a_mh   = 16u * (PX_STR * 2);
    const u32 b_off = (u32)((lane & 7) + ((lane & 8) ? 8 : 0)) * (PW_STR * 2) +
                      ((lane & 16) ? 16u : 0u);

    float4 xv[8];

    #pragma unroll
    for (int l = 0; l < 8; l++)
        xv[l] = *(const float4*)&X[(xrow0 + xr + l * 16) * DIN + xc];
    #pragma unroll
    for (int l = 0; l < 8; l++) {
        int r = xr + l * 16;
        u32 h0 = cvt2(xv[l].x, xv[l].y), h1 = cvt2(xv[l].z, xv[l].w);
        u32 l0 = cvt2(xv[l].x - bflo(h0), xv[l].y - bfhi(h0));
        u32 l1 = cvt2(xv[l].z - bflo(h1), xv[l].w - bfhi(h1));
        *(uint2*)&Xh[0][r * PX_STR + xc] = make_uint2(h0, h1);
        *(uint2*)&Xl[0][r * PX_STR + xc] = make_uint2(l0, l1);
    }
    {
        u32 wh_a = s2u(Wh[0]), wl_a = s2u(Wl[0]);
        #pragma unroll
        for (int l = 0; l < 4; l++) {
            int r = wr0 + l * 8;
            u32 so = (u32)(r * PW_STR + wc0) * 2;
            cp16(wh_a + so, gWh + (size_t)r * DHEAD + wc0);
            cp16(wl_a + so, gWl + (size_t)r * DHEAD + wc0);
        }
        CP_COMMIT();
    }

    for (int ks = 0; ks < DIN / 32; ks++) {
        const int cur = ks & 1;
        CP_WAIT0();
        __syncthreads();

        const bool more = (ks + 1) < DIN / 32;
        if (more) {
            #pragma unroll
            for (int l = 0; l < 8; l++)
                xv[l] = *(const float4*)&X[(xrow0 + xr + l * 16) * DIN +
                                           (ks + 1) * 32 + xc];
            u32 wh_a = s2u(Wh[cur ^ 1]), wl_a = s2u(Wl[cur ^ 1]);
            #pragma unroll
            for (int l = 0; l < 4; l++) {
                int r = wr0 + l * 8;
                u32 so = (u32)(r * PW_STR + wc0) * 2;
                size_t g = (size_t)((ks + 1) * 32 + r) * DHEAD + wc0;
                cp16(wh_a + so, gWh + g);
                cp16(wl_a + so, gWl + g);
            }
            CP_COMMIT();
        }

        const u32 xh_b = s2u(Xh[cur]), xl_b = s2u(Xl[cur]);
        const u32 wh_b = s2u(Wh[cur]), wl_b = s2u(Wl[cur]);
        #pragma unroll
        for (int kc = 0; kc < 2; kc++) {
            u32 ah[2][4], al[2][4];
            #pragma unroll
            for (int mh = 0; mh < 2; mh++) {
                ldm_x4(ah[mh][0], ah[mh][1], ah[mh][2], ah[mh][3],
                       xh_b + a_off0 + mh * a_mh + kc * 32);
                ldm_x4(al[mh][0], al[mh][1], al[mh][2], al[mh][3],
                       xl_b + a_off0 + mh * a_mh + kc * 32);
            }
            #pragma unroll
            for (int ntp = 0; ntp < 8; ntp++) {
                u32 bh0, bh1, bh2, bh3, bl0, bl1, bl2, bl3;
                u32 boff2 = b_off + (u32)(kc * 16) * (PW_STR * 2) + ntp * 32;
                ldm_x4t(bh0, bh1, bh2, bh3, wh_b + boff2);
                ldm_x4t(bl0, bl1, bl2, bl3, wl_b + boff2);
                #pragma unroll
                for (int mh = 0; mh < 2; mh++) {
                    mma16816(c[mh][2 * ntp], ah[mh][0], ah[mh][1], ah[mh][2], ah[mh][3], bh0, bh1);
                    mma16816(c[mh][2 * ntp], ah[mh][0], ah[mh][1], ah[mh][2], ah[mh][3], bl0, bl1);
                    mma16816(c[mh][2 * ntp], al[mh][0], al[mh][1], al[mh][2], al[mh][3], bh0, bh1);
                    mma16816(c[mh][2 * ntp + 1], ah[mh][0], ah[mh][1], ah[mh][2], ah[mh][3], bh2, bh3);
                    mma16816(c[mh][2 * ntp + 1], ah[mh][0], ah[mh][1], ah[mh][2], ah[mh][3], bl2, bl3);
                    mma16816(c[mh][2 * ntp + 1], al[mh][0], al[mh][1], al[mh][2], al[mh][3], bh2, bh3);
                }
            }
        }

        if (more) {
            #pragma unroll
            for (int l = 0; l < 8; l++) {
                int r = xr + l * 16;
                u32 h0 = cvt2(xv[l].x, xv[l].y), h1 = cvt2(xv[l].z, xv[l].w);
                u32 l0 = cvt2(xv[l].x - bflo(h0), xv[l].y - bfhi(h0));
                u32 l1 = cvt2(xv[l].z - bflo(h1), xv[l].w - bfhi(h1));
                *(uint2*)&Xh[cur ^ 1][r * PX_STR + xc] = make_uint2(h0, h1);
                *(uint2*)&Xl[cur ^ 1][r * PX_STR + xc] = make_uint2(l0, l1);
            }
        }
    }

    #pragma unroll
    for (int mh = 0; mh < 2; mh++) {
        const size_t r0 = xrow0 + wid * 32 + mh * 16 + (lane >> 2);
        const size_t r1 = r0 + 8;
        #pragma unroll
        for (int nt = 0; nt < 16; nt++) {
            int col = nt * 8 + (lane & 3) * 2;
            float b0 = bias[col], b1 = bias[col + 1];
            float v00 = c[mh][nt][0] + b0, v01 = c[mh][nt][1] + b1;
            float v10 = c[mh][nt][2] + b0, v11 = c[mh][nt][3] + b1;
            u32 h0 = cvt2(v00, v01), l0 = cvt2(v00 - bflo(h0), v01 - bfhi(h0));
            u32 h1 = cvt2(v10, v11), l1 = cvt2(v10 - bflo(h1), v11 - bfhi(h1));
            *(u32*)&outh[r0 * DHEAD + col] = h0;
            *(u32*)&outl[r0 * DHEAD + col] = l0;
            *(u32*)&outh[r1 * DHEAD + col] = h1;
            *(u32*)&outl[r1 * DHEAD + col] = l1;
        }
    }
}

// ---------------------------------------------------------------------------
// Flash attention: 128-row q-tiles, 8 warps (each m16), paired {15-bx, bx}.
// Same proven double-buffered cp.async K/V pipeline as round 8; dm in regs.
// 8 warps/SM (vs 4) at identical 209KB smem -> better MMA latency hiding.
// ---------------------------------------------------------------------------
#define AS_STR 136
#define AS_ELE (64 * AS_STR)            // u16 per 64-row array
#define Q_ELE  (128 * AS_STR)           // u16 per 128-row Q array
#define KV_STG (4 * AS_ELE * 2)         // bytes per K/V stage (Kh,Kl,Vh,Vl)
#define ATT_SMEM (2 * Q_ELE * 2 + 2 * KV_STG)   // 69632 + 139264 = 208896 B

__global__ __launch_bounds__(256) void attn_mma_kernel(
    const float* __restrict__ dm, float* __restrict__ out)
{
    extern __shared__ __align__(16) u16 sm_[];
    const u32 sb = s2u(sm_);
    const u32 qh_b = sb, ql_b = sb + Q_ELE * 2;
    const u32 kv_b = sb + 4 * Q_ELE;         // 2 Q arrays * 2 bytes
    const u32 OFF_KL = AS_ELE * 2;
    const u32 OFF_VH = 2 * AS_ELE * 2;
    const u32 OFF_VL = 3 * AS_ELE * 2;

    const int tid = threadIdx.x, lane = tid & 31, wid = tid >> 5;
    const int b = blockIdx.y;
    const size_t brow = (size_t)b * SEQ;

    const u32 a_off = (u32)(wid * 16 + (lane & 15)) * (AS_STR * 2) +
                      ((lane & 16) ? 16u : 0u);                      // A (plain)
    const u32 bk_off = (u32)((lane & 7) + ((lane & 16) ? 8 : 0)) * (AS_STR * 2) +
                       ((lane & 8) ? 16u : 0u);                      // B plain (K)
    const u32 bv_off = (u32)((lane & 7) + ((lane & 8) ? 8 : 0)) * (AS_STR * 2) +
                       ((lane & 16) ? 16u : 0u);                     // B trans (V)

    // staging maps (256 threads)
    const int sr  = tid >> 4;            // 0..15
    const int scu = (tid & 15) * 8;      // u16 col

    auto ldkv = [&](int kt) {
        const u32 st = kv_b + (u32)(kt & 1) * KV_STG;
        const int k1 = kt * 64;
        #pragma unroll
        for (int l2 = 0; l2 < 4; l2++) {
            int r = sr + l2 * 16;
            size_t g = (brow + k1 + r) * DHEAD + scu;
            u32 so = (u32)(r * AS_STR + scu) * 2;
            cp16(st + so,          g_Kh + g);
            cp16(st + OFF_KL + so, g_Kl + g);
            cp16(st + OFF_VH + so, g_Vh + g);
            cp16(st + OFF_VL + so, g_Vl + g);
        }
        CP_COMMIT();
    };

    for (int half = 0; half < 2; half++) {
        const int qt = half == 0 ? (15 - (int)blockIdx.x) : (int)blockIdx.x;
        const int q0 = qt * 128;
        const int nkt = 2 * qt + 2;          // 64-wide k-tiles

        __syncthreads();   // previous half fully done with all smem

        // stage Q tile (128 rows, hi & lo) — plain STS, ordered by next barrier
        #pragma unroll
        for (int l2 = 0; l2 < 8; l2++) {
            int idx = tid + l2 * 256;
            int r = idx >> 4, cu = (idx & 15) * 8;
            size_t g = (brow + q0 + r) * DHEAD + cu;
            *(uint4*)&sm_[r * AS_STR + cu]         = *(const uint4*)&g_Qh[g];
            *(uint4*)&sm_[Q_ELE + r * AS_STR + cu] = *(const uint4*)&g_Ql[g];
        }
        ldkv(0);

        float o[16][4];
        #pragma unroll
        for (int i = 0; i < 16; i++)
            #pragma unroll
            for (int j = 0; j < 4; j++) o[i][j] = 0.f;
        float m0 = -INFINITY, m1 = -INFINITY, l0 = 0.f, l1 = 0.f;

        const int rA = q0 + wid * 16 + (lane >> 2);
        const int rB = rA + 8;
        const int wmax = q0 + wid * 16 + 15;   // max q-row this warp owns

        for (int kt = 0; kt < nkt; kt++) {
            const int k0 = kt * 64;
            const bool active = (k0 <= wmax);  // warp-uniform causal skip

            float2 dmrA[8], dmrB[8];
            if (active) {
                const int kc0 = k0 + (lane & 3) * 2;
                #pragma unroll
                for (int nt = 0; nt < 8; nt++) {
                    dmrA[nt] = *(const float2*)&dm[(brow + rA) * SEQ + kc0 + nt * 8];
                    dmrB[nt] = *(const float2*)&dm[(brow + rB) * SEQ + kc0 + nt * 8];
                }
            }

            CP_WAIT0();
            __syncthreads();

            if (kt + 1 < nkt) ldkv(kt + 1);    // prefetch into other buffer

            if (active) {
                const u32 kh_b = kv_b + (u32)(kt & 1) * KV_STG;
                const u32 kl_b = kh_b + OFF_KL;
                const u32 vh_b = kh_b + OFF_VH;
                const u32 vl_b = kh_b + OFF_VL;

                // ---- S = Q K^T (16 x 64 per warp) ----
                float s[8][4];
                #pragma unroll
                for (int i = 0; i < 8; i++)
                    #pragma unroll
                    for (int j = 0; j < 4; j++) s[i][j] = 0.f;

                #pragma unroll
                for (int kc = 0; kc < 8; kc++) {
                    u32 ah0, ah1, ah2, ah3, al0, al1, al2, al3;
                    ldm_x4(ah0, ah1, ah2, ah3, qh_b + a_off + kc * 32);
                    ldm_x4(al0, al1, al2, al3, ql_b + a_off + kc * 32);
                    #pragma unroll
                    for (int ntp = 0; ntp < 4; ntp++) {
                        u32 bh0, bh1, bh2, bh3, bl0, bl1, bl2, bl3;
                        u32 off = bk_off + (u32)(ntp * 16) * (AS_STR * 2) + kc * 32;
                        ldm_x4(bh0, bh1, bh2, bh3, kh_b + off);
                        ldm_x4(bl0, bl1, bl2, bl3, kl_b + off);
                        mma16816(s[2 * ntp], ah0, ah1, ah2, ah3, bh0, bh1);
                        mma16816(s[2 * ntp], ah0, ah1, ah2, ah3, bl0, bl1);
                        mma16816(s[2 * ntp], al0, al1, al2, al3, bh0, bh1);
                        mma16816(s[2 * ntp + 1], ah0, ah1, ah2, ah3, bh2, bh3);
                        mma16816(s[2 * ntp + 1], ah0, ah1, ah2, ah3, bl2, bl3);
                        mma16816(s[2 * ntp + 1], al0, al1, al2, al3, bh2, bh3);
                    }
                }

                // ---- masking + online softmax ----
                float mx0 = -INFINITY, mx1 = -INFINITY;
                #pragma unroll
                for (int nt = 0; nt < 8; nt++) {
                    int kc0 = k0 + nt * 8 + (lane & 3) * 2;
                    if (kc0     > rA || s[nt][0] == 0.f) s[nt][0] = -INFINITY;
                    if (kc0 + 1 > rA || s[nt][1] == 0.f) s[nt][1] = -INFINITY;
                    if (kc0     > rB || s[nt][2] == 0.f) s[nt][2] = -INFINITY;
                    if (kc0 + 1 > rB || s[nt][3] == 0.f) s[nt][3] = -INFINITY;
                    mx0 = fmaxf(mx0, fmaxf(s[nt][0], s[nt][1]));
                    mx1 = fmaxf(mx1, fmaxf(s[nt][2], s[nt][3]));
                }
                mx0 = fmaxf(mx0, __shfl_xor_sync(0xffffffffu, mx0, 1));
                mx0 = fmaxf(mx0, __shfl_xor_sync(0xffffffffu, mx0, 2));
                mx1 = fmaxf(mx1, __shfl_xor_sync(0xffffffffu, mx1, 1));
                mx1 = fmaxf(mx1, __shfl_xor_sync(0xffffffffu, mx1, 2));

                float mn0 = fmaxf(m0, mx0), mn1 = fmaxf(m1, mx1);
                float sum0 = 0.f, sum1 = 0.f;
                #pragma unroll
                for (int nt = 0; nt < 8; nt++) {
                    s[nt][0] = __expf(s[nt][0] - mn0);
                    s[nt][1] = __expf(s[nt][1] - mn0);
                    s[nt][2] = __expf(s[nt][2] - mn1);
                    s[nt][3] = __expf(s[nt][3] - mn1);
                    sum0 += s[nt][0] + s[nt][1];
                    sum1 += s[nt][2] + s[nt][3];
                }
                sum0 += __shfl_xor_sync(0xffffffffu, sum0, 1);
                sum0 += __shfl_xor_sync(0xffffffffu, sum0, 2);
                sum1 += __shfl_xor_sync(0xffffffffu, sum1, 1);
                sum1 += __shfl_xor_sync(0xffffffffu, sum1, 2);

                float sc0 = __expf(m0 - mn0), sc1 = __expf(m1 - mn1);
                l0 = l0 * sc0 + sum0;  m0 = mn0;
                l1 = l1 * sc1 + sum1;  m1 = mn1;

                #pragma unroll
                for (int nt = 0; nt < 16; nt++) {
                    o[nt][0] *= sc0; o[nt][1] *= sc0;
                    o[nt][2] *= sc1; o[nt][3] *= sc1;
                }

                // ---- dropout mask (registers) ----
                #pragma unroll
                for (int nt = 0; nt < 8; nt++) {
                    s[nt][0] *= dmrA[nt].x; s[nt][1] *= dmrA[nt].y;
                    s[nt][2] *= dmrB[nt].x; s[nt][3] *= dmrB[nt].y;
                }

                // ---- O += P V ----
                #pragma unroll
                for (int tc = 0; tc < 4; tc++) {
                    u32 ph0 = cvt2(s[2 * tc][0], s[2 * tc][1]);
                    u32 pl0 = cvt2(s[2 * tc][0] - bflo(ph0), s[2 * tc][1] - bfhi(ph0));
                    u32 ph1 = cvt2(s[2 * tc][2], s[2 * tc][3]);
                    u32 pl1 = cvt2(s[2 * tc][2] - bflo(ph1), s[2 * tc][3] - bfhi(ph1));
                    u32 ph2 = cvt2(s[2 * tc + 1][0], s[2 * tc + 1][1]);
                    u32 pl2 = cvt2(s[2 * tc + 1][0] - bflo(ph2), s[2 * tc + 1][1] - bfhi(ph2));
                    u32 ph3 = cvt2(s[2 * tc + 1][2], s[2 * tc + 1][3]);
                    u32 pl3 = cvt2(s[2 * tc + 1][2] - bflo(ph3), s[2 * tc + 1][3] - bfhi(ph3));
                    #pragma unroll
                    for (int ntp = 0; ntp < 8; ntp++) {
                        u32 bh0, bh1, bh2, bh3, bl0, bl1, bl2, bl3;
                        u32 off = bv_off + (u32)(tc * 16) * (AS_STR * 2) + ntp * 32;
                        ldm_x4t(bh0, bh1, bh2, bh3, vh_b + off);
                        ldm_x4t(bl0, bl1, bl2, bl3, vl_b + off);
                        mma16816(o[2 * ntp], ph0, ph1, ph2, ph3, bh0, bh1);
                        mma16816(o[2 * ntp], ph0, ph1, ph2, ph3, bl0, bl1);
                        mma16816(o[2 * ntp], pl0, pl1, pl2, pl3, bh0, bh1);
                        mma16816(o[2 * ntp + 1], ph0, ph1, ph2, ph3, bh2, bh3);
                        mma16816(o[2 * ntp + 1], ph0, ph1, ph2, ph3, bl2, bl3);
                        mma16816(o[2 * ntp + 1], pl0, pl1, pl2, pl3, bh2, bh3);
                    }
                }
            } // active
        } // kt

        // ---- finalize ----
        float inv0 = 1.0f / l0, inv1 = 1.0f / l1;
        #pragma unroll
        for (int nt = 0; nt < 16; nt++) {
            int col = nt * 8 + (lane & 3) * 2;
            float2 v0 = make_float2(o[nt][0] * inv0, o[nt][1] * inv0);
            float2 v1 = make_float2(o[nt][2] * inv1, o[nt][3] * inv1);
            *(float2*)&out[(brow + rA) * DHEAD + col] = v0;
            *(float2*)&out[(brow + rB) * DHEAD + col] = v1;
        }
    } // half
}

// ---------------------------------------------------------------------------
extern "C" void kernel_launch(void* const* d_in, const int* in_sizes, int n_in,
                              void* d_out, int out_size)
{
    const float* X  = (const float*)d_in[0];
    const float* Wq = (const float*)d_in[1];
    const float* bq = (const float*)d_in[2];
    const float* Wk = (const float*)d_in[3];
    const float* bk = (const float*)d_in[4];
    const float* Wv = (const float*)d_in[5];
    const float* bv = (const float*)d_in[6];
    const float* dm = (const float*)d_in[7];
    float* out = (float*)d_out;

    split_w_kernel<<<384, 256>>>(Wq, Wk, Wv);

    cudaFuncSetAttribute(proj_mma_kernel,
                         cudaFuncAttributeMaxDynamicSharedMemorySize, PROJ_SMEM);
    dim3 gp(3, NROWS / 128);
    proj_mma_kernel<<<gp, 128, PROJ_SMEM>>>(X, bq, bk, bv);

    cudaFuncSetAttribute(attn_mma_kernel,
                         cudaFuncAttributeMaxDynamicSharedMemorySize, ATT_SMEM);
    dim3 ga(16, BATCH);
    attn_mma_kernel<<<ga, 256, ATT_SMEM>>>(dm, out);
}

// round 12
// speedup vs baseline: 1.1563x; 1.1563x over previous
#include <cuda_runtime.h>
#include <math.h>

#define BATCH 8
#define SEQ   2048
#define DIN   1024
#define DHEAD 128
#define NROWS (BATCH * SEQ)

typedef unsigned int  u32;
typedef unsigned short u16;

// ---------------------------------------------------------------------------
// split-bf16 global scratch
// ---------------------------------------------------------------------------
__device__ __align__(16) u16 g_Wh[3 * DIN * DHEAD];
__device__ __align__(16) u16 g_Wl[3 * DIN * DHEAD];
__device__ __align__(16) u16 g_Qh[NROWS * DHEAD];
__device__ __align__(16) u16 g_Ql[NROWS * DHEAD];
__device__ __align__(16) u16 g_Kh[NROWS * DHEAD];
__device__ __align__(16) u16 g_Kl[NROWS * DHEAD];
__device__ __align__(16) u16 g_Vh[NROWS * DHEAD];
__device__ __align__(16) u16 g_Vl[NROWS * DHEAD];

// ---------------------------------------------------------------------------
// helpers
// ---------------------------------------------------------------------------
__device__ __forceinline__ u32 cvt2(float lo, float hi) {  // bf16(lo)|bf16(hi)<<16
    u32 r; asm("cvt.rn.bf16x2.f32 %0, %1, %2;" : "=r"(r) : "f"(hi), "f"(lo));
    return r;
}
__device__ __forceinline__ float bflo(u32 v) { return __uint_as_float(v << 16); }
__device__ __forceinline__ float bfhi(u32 v) { return __uint_as_float(v & 0xffff0000u); }

__device__ __forceinline__ u32 s2u(const void* p) {
    u32 a;
    asm("{.reg .u64 t; cvta.to.shared.u64 t, %1; cvt.u32.u64 %0, t;}" : "=r"(a) : "l"(p));
    return a;
}
__device__ __forceinline__ void cp16(u32 smem, const void* g) {
    asm volatile("cp.async.cg.shared.global [%0], [%1], 16;" :: "r"(smem), "l"(g));
}
#define CP_COMMIT() asm volatile("cp.async.commit_group;")
#define CP_WAIT0()  asm volatile("cp.async.wait_group 0;")

__device__ __forceinline__ void ldm_x4(u32& r0, u32& r1, u32& r2, u32& r3, u32 a) {
    asm volatile("ldmatrix.sync.aligned.m8n8.x4.shared.b16 {%0,%1,%2,%3},[%4];"
                 : "=r"(r0), "=r"(r1), "=r"(r2), "=r"(r3) : "r"(a));
}
__device__ __forceinline__ void ldm_x4t(u32& r0, u32& r1, u32& r2, u32& r3, u32 a) {
    asm volatile("ldmatrix.sync.aligned.m8n8.x4.trans.shared.b16 {%0,%1,%2,%3},[%4];"
                 : "=r"(r0), "=r"(r1), "=r"(r2), "=r"(r3) : "r"(a));
}
__device__ __forceinline__ void mma16816(float c[4], u32 a0, u32 a1, u32 a2, u32 a3,
                                         u32 b0, u32 b1) {
    asm volatile(
        "mma.sync.aligned.m16n8k16.row.col.f32.bf16.bf16.f32 "
        "{%0,%1,%2,%3},{%4,%5,%6,%7},{%8,%9},{%0,%1,%2,%3};"
        : "+f"(c[0]), "+f"(c[1]), "+f"(c[2]), "+f"(c[3])
        : "r"(a0), "r"(a1), "r"(a2), "r"(a3), "r"(b0), "r"(b1));
}

// ---------------------------------------------------------------------------
// split pass for W only (X is converted in-kernel by proj)
// ---------------------------------------------------------------------------
__global__ void split_w_kernel(const float* __restrict__ Wq,
                               const float* __restrict__ Wk,
                               const float* __restrict__ Wv)
{
    const int per = DIN * DHEAD / 4;
    int i = blockIdx.x * blockDim.x + threadIdx.x;
    if (i >= 3 * per) return;
    const float* src = (i < per) ? Wq : (i < 2 * per) ? Wk : Wv;
    float4 v = ((const float4*)src)[i % per];
    u32 h0 = cvt2(v.x, v.y), h1 = cvt2(v.z, v.w);
    u32 l0 = cvt2(v.x - bflo(h0), v.y - bfhi(h0));
    u32 l1 = cvt2(v.z - bflo(h1), v.w - bfhi(h1));
    ((uint2*)g_Wh)[i] = make_uint2(h0, h1);
    ((uint2*)g_Wl)[i] = make_uint2(l0, l1);
}

// ---------------------------------------------------------------------------
// Projection GEMM (exact round-8 code — proven config).
// ---------------------------------------------------------------------------
#define PX_STR 40
#define PW_STR 136
#define PX_ELE (128 * PX_STR)
#define PW_ELE (32 * PW_STR)
#define PROJ_SMEM ((4 * PX_ELE + 4 * PW_ELE) * 2)   // 75776 B

__global__ __launch_bounds__(128) void proj_mma_kernel(
    const float* __restrict__ X,
    const float* __restrict__ bq, const float* __restrict__ bk,
    const float* __restrict__ bv)
{
    extern __shared__ __align__(16) u16 psm[];
    u16* Xh[2] = { psm,              psm + 2 * PX_ELE };
    u16* Xl[2] = { psm + PX_ELE,     psm + 3 * PX_ELE };
    u16* Wh[2] = { psm + 4 * PX_ELE,              psm + 4 * PX_ELE + 2 * PW_ELE };
    u16* Wl[2] = { psm + 4 * PX_ELE + PW_ELE,     psm + 4 * PX_ELE + 3 * PW_ELE };

    const int tid = threadIdx.x, lane = tid & 31, wid = tid >> 5;
    const int sel = blockIdx.x;
    const u16* gWh = g_Wh + sel * (DIN * DHEAD);
    const u16* gWl = g_Wl + sel * (DIN * DHEAD);
    const float* bias = (sel == 0) ? bq : (sel == 1) ? bk : bv;
    u16* outh = (sel == 0) ? g_Qh : (sel == 1) ? g_Kh : g_Vh;
    u16* outl = (sel == 0) ? g_Ql : (sel == 1) ? g_Kl : g_Vl;

    float c[2][16][4];
    #pragma unroll
    for (int mh = 0; mh < 2; mh++)
        #pragma unroll
        for (int i = 0; i < 16; i++)
            #pragma unroll
            for (int j = 0; j < 4; j++) c[mh][i][j] = 0.f;

    const size_t xrow0 = (size_t)blockIdx.y * 128;
    const int xr = tid >> 3, xc = (tid & 7) * 4;
    const int wr0 = tid >> 4, wc0 = (tid & 15) * 8;
    const u32 a_off0 = (u32)(wid * 32 + (lane & 15)) * (PX_STR * 2) +
                       ((lane & 16) ? 16u : 0u);
    const u32 a_mh   = 16u * (PX_STR * 2);
    const u32 b_off = (u32)((lane & 7) + ((lane & 8) ? 8 : 0)) * (PW_STR * 2) +
                      ((lane & 16) ? 16u : 0u);

    float4 xv[8];

    #pragma unroll
    for (int l = 0; l < 8; l++)
        xv[l] = *(const float4*)&X[(xrow0 + xr + l * 16) * DIN + xc];
    #pragma unroll
    for (int l = 0; l < 8; l++) {
        int r = xr + l * 16;
        u32 h0 = cvt2(xv[l].x, xv[l].y), h1 = cvt2(xv[l].z, xv[l].w);
        u32 l0 = cvt2(xv[l].x - bflo(h0), xv[l].y - bfhi(h0));
        u32 l1 = cvt2(xv[l].z - bflo(h1), xv[l].w - bfhi(h1));
        *(uint2*)&Xh[0][r * PX_STR + xc] = make_uint2(h0, h1);
        *(uint2*)&Xl[0][r * PX_STR + xc] = make_uint2(l0, l1);
    }
    {
        u32 wh_a = s2u(Wh[0]), wl_a = s2u(Wl[0]);
        #pragma unroll
        for (int l = 0; l < 4; l++) {
            int r = wr0 + l * 8;
            u32 so = (u32)(r * PW_STR + wc0) * 2;
            cp16(wh_a + so, gWh + (size_t)r * DHEAD + wc0);
            cp16(wl_a + so, gWl + (size_t)r * DHEAD + wc0);
        }
        CP_COMMIT();
    }

    for (int ks = 0; ks < DIN / 32; ks++) {
        const int cur = ks & 1;
        CP_WAIT0();
        __syncthreads();

        const bool more = (ks + 1) < DIN / 32;
        if (more) {
            #pragma unroll
            for (int l = 0; l < 8; l++)
                xv[l] = *(const float4*)&X[(xrow0 + xr + l * 16) * DIN +
                                           (ks + 1) * 32 + xc];
            u32 wh_a = s2u(Wh[cur ^ 1]), wl_a = s2u(Wl[cur ^ 1]);
            #pragma unroll
            for (int l = 0; l < 4; l++) {
                int r = wr0 + l * 8;
                u32 so = (u32)(r * PW_STR + wc0) * 2;
                size_t g = (size_t)((ks + 1) * 32 + r) * DHEAD + wc0;
                cp16(wh_a + so, gWh + g);
                cp16(wl_a + so, gWl + g);
            }
            CP_COMMIT();
        }

        const u32 xh_b = s2u(Xh[cur]), xl_b = s2u(Xl[cur]);
        const u32 wh_b = s2u(Wh[cur]), wl_b = s2u(Wl[cur]);
        #pragma unroll
        for (int kc = 0; kc < 2; kc++) {
            u32 ah[2][4], al[2][4];
            #pragma unroll
            for (int mh = 0; mh < 2; mh++) {
                ldm_x4(ah[mh][0], ah[mh][1], ah[mh][2], ah[mh][3],
                       xh_b + a_off0 + mh * a_mh + kc * 32);
                ldm_x4(al[mh][0], al[mh][1], al[mh][2], al[mh][3],
                       xl_b + a_off0 + mh * a_mh + kc * 32);
            }
            #pragma unroll
            for (int ntp = 0; ntp < 8; ntp++) {
                u32 bh0, bh1, bh2, bh3, bl0, bl1, bl2, bl3;
                u32 boff2 = b_off + (u32)(kc * 16) * (PW_STR * 2) + ntp * 32;
                ldm_x4t(bh0, bh1, bh2, bh3, wh_b + boff2);
                ldm_x4t(bl0, bl1, bl2, bl3, wl_b + boff2);
                #pragma unroll
                for (int mh = 0; mh < 2; mh++) {
                    mma16816(c[mh][2 * ntp], ah[mh][0], ah[mh][1], ah[mh][2], ah[mh][3], bh0, bh1);
                    mma16816(c[mh][2 * ntp], ah[mh][0], ah[mh][1], ah[mh][2], ah[mh][3], bl0, bl1);
                    mma16816(c[mh][2 * ntp], al[mh][0], al[mh][1], al[mh][2], al[mh][3], bh0, bh1);
                    mma16816(c[mh][2 * ntp + 1], ah[mh][0], ah[mh][1], ah[mh][2], ah[mh][3], bh2, bh3);
                    mma16816(c[mh][2 * ntp + 1], ah[mh][0], ah[mh][1], ah[mh][2], ah[mh][3], bl2, bl3);
                    mma16816(c[mh][2 * ntp + 1], al[mh][0], al[mh][1], al[mh][2], al[mh][3], bh2, bh3);
                }
            }
        }

        if (more) {
            #pragma unroll
            for (int l = 0; l < 8; l++) {
                int r = xr + l * 16;
                u32 h0 = cvt2(xv[l].x, xv[l].y), h1 = cvt2(xv[l].z, xv[l].w);
                u32 l0 = cvt2(xv[l].x - bflo(h0), xv[l].y - bfhi(h0));
                u32 l1 = cvt2(xv[l].z - bflo(h1), xv[l].w - bfhi(h1));
                *(uint2*)&Xh[cur ^ 1][r * PX_STR + xc] = make_uint2(h0, h1);
                *(uint2*)&Xl[cur ^ 1][r * PX_STR + xc] = make_uint2(l0, l1);
            }
        }
    }

    #pragma unroll
    for (int mh = 0; mh < 2; mh++) {
        const size_t r0 = xrow0 + wid * 32 + mh * 16 + (lane >> 2);
        const size_t r1 = r0 + 8;
        #pragma unroll
        for (int nt = 0; nt < 16; nt++) {
            int col = nt * 8 + (lane & 3) * 2;
            float b0 = bias[col], b1 = bias[col + 1];
            float v00 = c[mh][nt][0] + b0, v01 = c[mh][nt][1] + b1;
            float v10 = c[mh][nt][2] + b0, v11 = c[mh][nt][3] + b1;
            u32 h0 = cvt2(v00, v01), l0 = cvt2(v00 - bflo(h0), v01 - bfhi(h0));
            u32 h1 = cvt2(v10, v11), l1 = cvt2(v10 - bflo(h1), v11 - bfhi(h1));
            *(u32*)&outh[r0 * DHEAD + col] = h0;
            *(u32*)&outl[r0 * DHEAD + col] = l0;
            *(u32*)&outh[r1 * DHEAD + col] = h1;
            *(u32*)&outl[r1 * DHEAD + col] = l1;
        }
    }
}

// ---------------------------------------------------------------------------
// Flash attention — round-8 structure (proven), two deltas:
//  * drop_mask in registers (LDG issued before CP_WAIT0; hidden by pipeline)
//  * Q staged via cp.async in the same group as K/V tile 0
// 128 threads (4 warps), paired q-tiles {31-bx, bx}, double-buffered K/V.
// ---------------------------------------------------------------------------
#define AS_STR 136
#define AS_ELE (64 * AS_STR)
#define KV_STG (4 * AS_ELE * 2)
#define ATT_SMEM (2 * AS_ELE * 2 + 2 * KV_STG)   // 174080 B

__global__ __launch_bounds__(128) void attn_mma_kernel(
    const float* __restrict__ dm, float* __restrict__ out)
{
    extern __shared__ __align__(16) u16 sm_[];
    const u32 sb = s2u(sm_);
    const u32 qh_b = sb;
    const u32 ql_b = qh_b + AS_ELE * 2;
    const u32 kv_b = ql_b + AS_ELE * 2;
    const u32 OFF_KL = AS_ELE * 2;
    const u32 OFF_VH = 2 * AS_ELE * 2;
    const u32 OFF_VL = 3 * AS_ELE * 2;

    const int tid = threadIdx.x, lane = tid & 31, wid = tid >> 5;
    const int b = blockIdx.y;
    const size_t brow = (size_t)b * SEQ;

    const u32 a_off = (u32)(wid * 16 + (lane & 15)) * (AS_STR * 2) +
                      ((lane & 16) ? 16u : 0u);                      // A (plain)
    const u32 bk_off = (u32)((lane & 7) + ((lane & 16) ? 8 : 0)) * (AS_STR * 2) +
                       ((lane & 8) ? 16u : 0u);                      // B plain (K)
    const u32 bv_off = (u32)((lane & 7) + ((lane & 8) ? 8 : 0)) * (AS_STR * 2) +
                       ((lane & 16) ? 16u : 0u);                     // B trans (V)

    // staging maps
    const int sr  = tid >> 4;            // +8 per l2 (8 iters -> 64 rows)
    const int scu = (tid & 15) * 8;      // u16 col

    for (int half = 0; half < 2; half++) {
        const int qt = half == 0 ? (31 - (int)blockIdx.x) : (int)blockIdx.x;
        const int q0 = qt * 64;

        __syncthreads();   // protect smem reuse across halves

        // stage Q tile (hi & lo) via cp.async + K/V tile 0, one group
        #pragma unroll
        for (int l2 = 0; l2 < 8; l2++) {
            int r = sr + l2 * 8;
            size_t g = (brow + q0 + r) * DHEAD + scu;
            u32 so = (u32)(r * AS_STR + scu) * 2;
            cp16(qh_b + so, g_Qh + g);
            cp16(ql_b + so, g_Ql + g);
        }
        {
            const u32 st = kv_b;
            #pragma unroll
            for (int l2 = 0; l2 < 8; l2++) {
                int r = sr + l2 * 8;
                size_t g = (brow + 0 + r) * DHEAD + scu;
                u32 so = (u32)(r * AS_STR + scu) * 2;
                cp16(st + so,          g_Kh + g);
                cp16(st + OFF_KL + so, g_Kl + g);
                cp16(st + OFF_VH + so, g_Vh + g);
                cp16(st + OFF_VL + so, g_Vl + g);
            }
            CP_COMMIT();
        }

        float o[16][4];
        #pragma unroll
        for (int i = 0; i < 16; i++)
            #pragma unroll
            for (int j = 0; j < 4; j++) o[i][j] = 0.f;
        float m0 = -INFINITY, m1 = -INFINITY, l0 = 0.f, l1 = 0.f;

        const int rA = q0 + wid * 16 + (lane >> 2);
        const int rB = rA + 8;

        for (int kt = 0; kt <= qt; kt++) {
            const int cur = kt & 1;
            const int k0 = kt * 64;

            // dm -> registers; LDG latency hidden behind cp-wait + S-MMA
            float2 dmrA[8], dmrB[8];
            {
                const int kc0 = k0 + (lane & 3) * 2;
                #pragma unroll
                for (int nt = 0; nt < 8; nt++) {
                    dmrA[nt] = *(const float2*)&dm[(brow + rA) * SEQ + kc0 + nt * 8];
                    dmrB[nt] = *(const float2*)&dm[(brow + rB) * SEQ + kc0 + nt * 8];
                }
            }

            CP_WAIT0();
            __syncthreads();

            if (kt < qt) {  // prefetch next K/V stage
                const int k1 = (kt + 1) * 64;
                const u32 st = kv_b + (u32)(cur ^ 1) * KV_STG;
                #pragma unroll
                for (int l2 = 0; l2 < 8; l2++) {
                    int r = sr + l2 * 8;
                    size_t g = (brow + k1 + r) * DHEAD + scu;
                    u32 so = (u32)(r * AS_STR + scu) * 2;
                    cp16(st + so,          g_Kh + g);
                    cp16(st + OFF_KL + so, g_Kl + g);
                    cp16(st + OFF_VH + so, g_Vh + g);
                    cp16(st + OFF_VL + so, g_Vl + g);
                }
                CP_COMMIT();
            }

            const u32 kh_b = kv_b + (u32)cur * KV_STG;
            const u32 kl_b = kh_b + OFF_KL;
            const u32 vh_b = kh_b + OFF_VH;
            const u32 vl_b = kh_b + OFF_VL;

            // ---- S = Q K^T (16 x 64 per warp) ----
            float s[8][4];
            #pragma unroll
            for (int i = 0; i < 8; i++)
                #pragma unroll
                for (int j = 0; j < 4; j++) s[i][j] = 0.f;

            #pragma unroll
            for (int kc = 0; kc < 8; kc++) {
                u32 ah0, ah1, ah2, ah3, al0, al1, al2, al3;
                ldm_x4(ah0, ah1, ah2, ah3, qh_b + a_off + kc * 32);
                ldm_x4(al0, al1, al2, al3, ql_b + a_off + kc * 32);
                #pragma unroll
                for (int ntp = 0; ntp < 4; ntp++) {
                    u32 bh0, bh1, bh2, bh3, bl0, bl1, bl2, bl3;
                    u32 off = bk_off + (u32)(ntp * 16) * (AS_STR * 2) + kc * 32;
                    ldm_x4(bh0, bh1, bh2, bh3, kh_b + off);
                    ldm_x4(bl0, bl1, bl2, bl3, kl_b + off);
                    mma16816(s[2 * ntp], ah0, ah1, ah2, ah3, bh0, bh1);
                    mma16816(s[2 * ntp], ah0, ah1, ah2, ah3, bl0, bl1);
                    mma16816(s[2 * ntp], al0, al1, al2, al3, bh0, bh1);
                    mma16816(s[2 * ntp + 1], ah0, ah1, ah2, ah3, bh2, bh3);
                    mma16816(s[2 * ntp + 1], ah0, ah1, ah2, ah3, bl2, bl3);
                    mma16816(s[2 * ntp + 1], al0, al1, al2, al3, bh2, bh3);
                }
            }

            // ---- masking + online softmax ----
            float mx0 = -INFINITY, mx1 = -INFINITY;
            #pragma unroll
            for (int nt = 0; nt < 8; nt++) {
                int kc0 = k0 + nt * 8 + (lane & 3) * 2;
                if (kc0     > rA || s[nt][0] == 0.f) s[nt][0] = -INFINITY;
                if (kc0 + 1 > rA || s[nt][1] == 0.f) s[nt][1] = -INFINITY;
                if (kc0     > rB || s[nt][2] == 0.f) s[nt][2] = -INFINITY;
                if (kc0 + 1 > rB || s[nt][3] == 0.f) s[nt][3] = -INFINITY;
                mx0 = fmaxf(mx0, fmaxf(s[nt][0], s[nt][1]));
                mx1 = fmaxf(mx1, fmaxf(s[nt][2], s[nt][3]));
            }
            mx0 = fmaxf(mx0, __shfl_xor_sync(0xffffffffu, mx0, 1));
            mx0 = fmaxf(mx0, __shfl_xor_sync(0xffffffffu, mx0, 2));
            mx1 = fmaxf(mx1, __shfl_xor_sync(0xffffffffu, mx1, 1));
            mx1 = fmaxf(mx1, __shfl_xor_sync(0xffffffffu, mx1, 2));

            float mn0 = fmaxf(m0, mx0), mn1 = fmaxf(m1, mx1);
            float sum0 = 0.f, sum1 = 0.f;
            #pragma unroll
            for (int nt = 0; nt < 8; nt++) {
                s[nt][0] = __expf(s[nt][0] - mn0);
                s[nt][1] = __expf(s[nt][1] - mn0);
                s[nt][2] = __expf(s[nt][2] - mn1);
                s[nt][3] = __expf(s[nt][3] - mn1);
                sum0 += s[nt][0] + s[nt][1];
                sum1 += s[nt][2] + s[nt][3];
            }
            sum0 += __shfl_xor_sync(0xffffffffu, sum0, 1);
            sum0 += __shfl_xor_sync(0xffffffffu, sum0, 2);
            sum1 += __shfl_xor_sync(0xffffffffu, sum1, 1);
            sum1 += __shfl_xor_sync(0xffffffffu, sum1, 2);

            float sc0 = __expf(m0 - mn0), sc1 = __expf(m1 - mn1);
            l0 = l0 * sc0 + sum0;  m0 = mn0;
            l1 = l1 * sc1 + sum1;  m1 = mn1;

            #pragma unroll
            for (int nt = 0; nt < 16; nt++) {
                o[nt][0] *= sc0; o[nt][1] *= sc0;
                o[nt][2] *= sc1; o[nt][3] *= sc1;
            }

            // ---- dropout mask (registers) ----
            #pragma unroll
            for (int nt = 0; nt < 8; nt++) {
                s[nt][0] *= dmrA[nt].x; s[nt][1] *= dmrA[nt].y;
                s[nt][2] *= dmrB[nt].x; s[nt][3] *= dmrB[nt].y;
            }

            // ---- O += P V ----
            #pragma unroll
            for (int tc = 0; tc < 4; tc++) {
                u32 ph0 = cvt2(s[2 * tc][0], s[2 * tc][1]);
                u32 pl0 = cvt2(s[2 * tc][0] - bflo(ph0), s[2 * tc][1] - bfhi(ph0));
                u32 ph1 = cvt2(s[2 * tc][2], s[2 * tc][3]);
                u32 pl1 = cvt2(s[2 * tc][2] - bflo(ph1), s[2 * tc][3] - bfhi(ph1));
                u32 ph2 = cvt2(s[2 * tc + 1][0], s[2 * tc + 1][1]);
                u32 pl2 = cvt2(s[2 * tc + 1][0] - bflo(ph2), s[2 * tc + 1][1] - bfhi(ph2));
                u32 ph3 = cvt2(s[2 * tc + 1][2], s[2 * tc + 1][3]);
                u32 pl3 = cvt2(s[2 * tc + 1][2] - bflo(ph3), s[2 * tc + 1][3] - bfhi(ph3));
                #pragma unroll
                for (int ntp = 0; ntp < 8; ntp++) {
                    u32 bh0, bh1, bh2, bh3, bl0, bl1, bl2, bl3;
                    u32 off = bv_off + (u32)(tc * 16) * (AS_STR * 2) + ntp * 32;
                    ldm_x4t(bh0, bh1, bh2, bh3, vh_b + off);
                    ldm_x4t(bl0, bl1, bl2, bl3, vl_b + off);
                    mma16816(o[2 * ntp], ph0, ph1, ph2, ph3, bh0, bh1);
                    mma16816(o[2 * ntp], ph0, ph1, ph2, ph3, bl0, bl1);
                    mma16816(o[2 * ntp], pl0, pl1, pl2, pl3, bh0, bh1);
                    mma16816(o[2 * ntp + 1], ph0, ph1, ph2, ph3, bh2, bh3);
                    mma16816(o[2 * ntp + 1], ph0, ph1, ph2, ph3, bl2, bl3);
                    mma16816(o[2 * ntp + 1], pl0, pl1, pl2, pl3, bh2, bh3);
                }
            }
        } // kt

        // ---- finalize ----
        float inv0 = 1.0f / l0, inv1 = 1.0f / l1;
        #pragma unroll
        for (int nt = 0; nt < 16; nt++) {
            int col = nt * 8 + (lane & 3) * 2;
            float2 v0 = make_float2(o[nt][0] * inv0, o[nt][1] * inv0);
            float2 v1 = make_float2(o[nt][2] * inv1, o[nt][3] * inv1);
            *(float2*)&out[(brow + rA) * DHEAD + col] = v0;
            *(float2*)&out[(brow + rB) * DHEAD + col] = v1;
        }
    } // half
}

// ---------------------------------------------------------------------------
extern "C" void kernel_launch(void* const* d_in, const int* in_sizes, int n_in,
                              void* d_out, int out_size)
{
    const float* X  = (const float*)d_in[0];
    const float* Wq = (const float*)d_in[1];
    const float* bq = (const float*)d_in[2];
    const float* Wk = (const float*)d_in[3];
    const float* bk = (const float*)d_in[4];
    const float* Wv = (const float*)d_in[5];
    const float* bv = (const float*)d_in[6];
    const float* dm = (const float*)d_in[7];
    float* out = (float*)d_out;

    split_w_kernel<<<384, 256>>>(Wq, Wk, Wv);

    cudaFuncSetAttribute(proj_mma_kernel,
                         cudaFuncAttributeMaxDynamicSharedMemorySize, PROJ_SMEM);
    dim3 gp(3, NROWS / 128);
    proj_mma_kernel<<<gp, 128, PROJ_SMEM>>>(X, bq, bk, bv);

    cudaFuncSetAttribute(attn_mma_kernel,
                         cudaFuncAttributeMaxDynamicSharedMemorySize, ATT_SMEM);
    dim3 ga(16, BATCH);
    attn_mma_kernel<<<ga, 128, ATT_SMEM>>>(dm, out);
}

// round 13
// speedup vs baseline: 1.3323x; 1.1522x over previous
#include <cuda_runtime.h>
#include <math.h>

#define BATCH 8
#define SEQ   2048
#define DIN   1024
#define DHEAD 128
#define NROWS (BATCH * SEQ)

typedef unsigned int  u32;
typedef unsigned short u16;

// ---------------------------------------------------------------------------
// split-bf16 global scratch
// ---------------------------------------------------------------------------
__device__ __align__(16) u16 g_Wh[3 * DIN * DHEAD];
__device__ __align__(16) u16 g_Wl[3 * DIN * DHEAD];
__device__ __align__(16) u16 g_Qh[NROWS * DHEAD];
__device__ __align__(16) u16 g_Ql[NROWS * DHEAD];
__device__ __align__(16) u16 g_Kh[NROWS * DHEAD];
__device__ __align__(16) u16 g_Kl[NROWS * DHEAD];
__device__ __align__(16) u16 g_Vh[NROWS * DHEAD];
__device__ __align__(16) u16 g_Vl[NROWS * DHEAD];

// ---------------------------------------------------------------------------
// helpers
// ---------------------------------------------------------------------------
__device__ __forceinline__ u32 cvt2(float lo, float hi) {  // bf16(lo)|bf16(hi)<<16
    u32 r; asm("cvt.rn.bf16x2.f32 %0, %1, %2;" : "=r"(r) : "f"(hi), "f"(lo));
    return r;
}
__device__ __forceinline__ float bflo(u32 v) { return __uint_as_float(v << 16); }
__device__ __forceinline__ float bfhi(u32 v) { return __uint_as_float(v & 0xffff0000u); }

__device__ __forceinline__ u32 s2u(const void* p) {
    u32 a;
    asm("{.reg .u64 t; cvta.to.shared.u64 t, %1; cvt.u32.u64 %0, t;}" : "=r"(a) : "l"(p));
    return a;
}
__device__ __forceinline__ void cp16(u32 smem, const void* g) {
    asm volatile("cp.async.cg.shared.global [%0], [%1], 16;" :: "r"(smem), "l"(g));
}
#define CP_COMMIT() asm volatile("cp.async.commit_group;")
#define CP_WAIT0()  asm volatile("cp.async.wait_group 0;")

__device__ __forceinline__ void ldm_x4(u32& r0, u32& r1, u32& r2, u32& r3, u32 a) {
    asm volatile("ldmatrix.sync.aligned.m8n8.x4.shared.b16 {%0,%1,%2,%3},[%4];"
                 : "=r"(r0), "=r"(r1), "=r"(r2), "=r"(r3) : "r"(a));
}
__device__ __forceinline__ void ldm_x4t(u32& r0, u32& r1, u32& r2, u32& r3, u32 a) {
    asm volatile("ldmatrix.sync.aligned.m8n8.x4.trans.shared.b16 {%0,%1,%2,%3},[%4];"
                 : "=r"(r0), "=r"(r1), "=r"(r2), "=r"(r3) : "r"(a));
}
__device__ __forceinline__ void mma16816(float c[4], u32 a0, u32 a1, u32 a2, u32 a3,
                                         u32 b0, u32 b1) {
    asm volatile(
        "mma.sync.aligned.m16n8k16.row.col.f32.bf16.bf16.f32 "
        "{%0,%1,%2,%3},{%4,%5,%6,%7},{%8,%9},{%0,%1,%2,%3};"
        : "+f"(c[0]), "+f"(c[1]), "+f"(c[2]), "+f"(c[3])
        : "r"(a0), "r"(a1), "r"(a2), "r"(a3), "r"(b0), "r"(b1));
}

// ---------------------------------------------------------------------------
// split pass for W only (X is converted in-kernel by proj)
// ---------------------------------------------------------------------------
__global__ void split_w_kernel(const float* __restrict__ Wq,
                               const float* __restrict__ Wk,
                               const float* __restrict__ Wv)
{
    const int per = DIN * DHEAD / 4;
    int i = blockIdx.x * blockDim.x + threadIdx.x;
    if (i >= 3 * per) return;
    const float* src = (i < per) ? Wq : (i < 2 * per) ? Wk : Wv;
    float4 v = ((const float4*)src)[i % per];
    u32 h0 = cvt2(v.x, v.y), h1 = cvt2(v.z, v.w);
    u32 l0 = cvt2(v.x - bflo(h0), v.y - bfhi(h0));
    u32 l1 = cvt2(v.z - bflo(h1), v.w - bfhi(h1));
    ((uint2*)g_Wh)[i] = make_uint2(h0, h1);
    ((uint2*)g_Wl)[i] = make_uint2(l0, l1);
}

// ---------------------------------------------------------------------------
// Fused projection GEMM: ONE CTA computes Q, K and V for its 64 X-rows.
// X is loaded+converted ONCE per k-step and reused for 3x the MMA work
// (the conversion was ~45% of issue slots when done per-projection).
// W tiles stream through a per-(ks,sel)-step double-buffered cp.async
// pipeline. Per-output MMA order identical to prior rounds (same rel_err).
// 128 threads, 4 warps each m16 x N128. Grid 256 CTAs, 2 CTAs/SM.
// ---------------------------------------------------------------------------
#define PX_STR 40
#define PW_STR 136
#define PX_ELE (64 * PX_STR)           // u16 per X array per stage
#define PW_ELE (32 * PW_STR)           // u16 per W array per stage
#define PROJ_SMEM ((4 * PX_ELE + 4 * PW_ELE) * 2)   // 55296 B

__global__ __launch_bounds__(128) void proj_mma_kernel(
    const float* __restrict__ X,
    const float* __restrict__ bq, const float* __restrict__ bk,
    const float* __restrict__ bv)
{
    extern __shared__ __align__(16) u16 psm[];
    u16* Xh[2] = { psm,              psm + 2 * PX_ELE };
    u16* Xl[2] = { psm + PX_ELE,     psm + 3 * PX_ELE };
    u16* Wh[2] = { psm + 4 * PX_ELE,              psm + 4 * PX_ELE + 2 * PW_ELE };
    u16* Wl[2] = { psm + 4 * PX_ELE + PW_ELE,     psm + 4 * PX_ELE + 3 * PW_ELE };

    const int tid = threadIdx.x, lane = tid & 31, wid = tid >> 5;

    const u16* gWh[3] = { g_Wh, g_Wh + DIN * DHEAD, g_Wh + 2 * DIN * DHEAD };
    const u16* gWl[3] = { g_Wl, g_Wl + DIN * DHEAD, g_Wl + 2 * DIN * DHEAD };
    const float* bias[3] = { bq, bk, bv };
    u16* outh[3] = { g_Qh, g_Kh, g_Vh };
    u16* outl[3] = { g_Ql, g_Kl, g_Vl };

    float c[3][16][4];
    #pragma unroll
    for (int s3 = 0; s3 < 3; s3++)
        #pragma unroll
        for (int i = 0; i < 16; i++)
            #pragma unroll
            for (int j = 0; j < 4; j++) c[s3][i][j] = 0.f;

    const size_t xrow0 = (size_t)blockIdx.x * 64;
    // X ldg/sts mapping: 4 float4 per thread (64 rows x 32 cols)
    const int xr = tid >> 3, xc = (tid & 7) * 4;           // +16 rows per l
    // W cp.async mapping: 4 chunks per thread per array
    const int wr0 = tid >> 4, wc0 = (tid & 15) * 8;        // +8 rows per l
    // ldmatrix offsets
    const u32 a_off = (u32)(wid * 16 + (lane & 15)) * (PX_STR * 2) +
                      ((lane & 16) ? 16u : 0u);
    const u32 b_off = (u32)((lane & 7) + ((lane & 8) ? 8 : 0)) * (PW_STR * 2) +
                      ((lane & 16) ? 16u : 0u);

    auto cpw = [&](int sel, int ks, int buf) {
        u32 wh_a = s2u(Wh[buf]), wl_a = s2u(Wl[buf]);
        #pragma unroll
        for (int l = 0; l < 4; l++) {
            int r = wr0 + l * 8;
            u32 so = (u32)(r * PW_STR + wc0) * 2;
            size_t g = (size_t)(ks * 32 + r) * DHEAD + wc0;
            cp16(wh_a + so, gWh[sel] + g);
            cp16(wl_a + so, gWl[sel] + g);
        }
        CP_COMMIT();
    };

    float4 xv[4];

    // ---- prologue: convert X(ks=0) into X[0]; prefetch W(ks=0,sel=0) ----
    #pragma unroll
    for (int l = 0; l < 4; l++)
        xv[l] = *(const float4*)&X[(xrow0 + xr + l * 16) * DIN + xc];
    #pragma unroll
    for (int l = 0; l < 4; l++) {
        int r = xr + l * 16;
        u32 h0 = cvt2(xv[l].x, xv[l].y), h1 = cvt2(xv[l].z, xv[l].w);
        u32 l0 = cvt2(xv[l].x - bflo(h0), xv[l].y - bfhi(h0));
        u32 l1 = cvt2(xv[l].z - bflo(h1), xv[l].w - bfhi(h1));
        *(uint2*)&Xh[0][r * PX_STR + xc] = make_uint2(h0, h1);
        *(uint2*)&Xl[0][r * PX_STR + xc] = make_uint2(l0, l1);
    }
    cpw(0, 0, 0);

    for (int ks = 0; ks < DIN / 32; ks++) {
        const int xbuf = ks & 1;
        const bool morek = (ks + 1) < DIN / 32;

        // issue next X loads early: latency hidden behind this ks's 3 MMA steps
        if (morek) {
            #pragma unroll
            for (int l = 0; l < 4; l++)
                xv[l] = *(const float4*)&X[(xrow0 + xr + l * 16) * DIN +
                                           (ks + 1) * 32 + xc];
        }

        const u32 xh_b = s2u(Xh[xbuf]), xl_b = s2u(Xl[xbuf]);

        #pragma unroll
        for (int sel = 0; sel < 3; sel++) {
            const int wbuf = (ks + sel) & 1;          // step parity (3 odd)
            CP_WAIT0();
            __syncthreads();

            // prefetch W for next step
            if (sel < 2)       cpw(sel + 1, ks, wbuf ^ 1);
            else if (morek)    cpw(0, ks + 1, wbuf ^ 1);

            const u32 wh_b = s2u(Wh[wbuf]), wl_b = s2u(Wl[wbuf]);
            #pragma unroll
            for (int kc = 0; kc < 2; kc++) {
                u32 ah0, ah1, ah2, ah3, al0, al1, al2, al3;
                ldm_x4(ah0, ah1, ah2, ah3, xh_b + a_off + kc * 32);
                ldm_x4(al0, al1, al2, al3, xl_b + a_off + kc * 32);
                #pragma unroll
                for (int ntp = 0; ntp < 8; ntp++) {
                    u32 bh0, bh1, bh2, bh3, bl0, bl1, bl2, bl3;
                    u32 boff2 = b_off + (u32)(kc * 16) * (PW_STR * 2) + ntp * 32;
                    ldm_x4t(bh0, bh1, bh2, bh3, wh_b + boff2);
                    ldm_x4t(bl0, bl1, bl2, bl3, wl_b + boff2);
                    mma16816(c[sel][2 * ntp], ah0, ah1, ah2, ah3, bh0, bh1);
                    mma16816(c[sel][2 * ntp], ah0, ah1, ah2, ah3, bl0, bl1);
                    mma16816(c[sel][2 * ntp], al0, al1, al2, al3, bh0, bh1);
                    mma16816(c[sel][2 * ntp + 1], ah0, ah1, ah2, ah3, bh2, bh3);
                    mma16816(c[sel][2 * ntp + 1], ah0, ah1, ah2, ah3, bl2, bl3);
                    mma16816(c[sel][2 * ntp + 1], al0, al1, al2, al3, bh2, bh3);
                }
            }

            // convert & store next X tile during the last sel step
            if (sel == 2 && morek) {
                #pragma unroll
                for (int l = 0; l < 4; l++) {
                    int r = xr + l * 16;
                    u32 h0 = cvt2(xv[l].x, xv[l].y), h1 = cvt2(xv[l].z, xv[l].w);
                    u32 l0 = cvt2(xv[l].x - bflo(h0), xv[l].y - bfhi(h0));
                    u32 l1 = cvt2(xv[l].z - bflo(h1), xv[l].w - bfhi(h1));
                    *(uint2*)&Xh[xbuf ^ 1][r * PX_STR + xc] = make_uint2(h0, h1);
                    *(uint2*)&Xl[xbuf ^ 1][r * PX_STR + xc] = make_uint2(l0, l1);
                }
            }
        }
    }

    // ---- epilogue: +bias, split to bf16 pairs, store (3 outputs) ----
    const size_t r0 = xrow0 + wid * 16 + (lane >> 2);
    const size_t r1 = r0 + 8;
    #pragma unroll
    for (int sel = 0; sel < 3; sel++) {
        #pragma unroll
        for (int nt = 0; nt < 16; nt++) {
            int col = nt * 8 + (lane & 3) * 2;
            float b0 = bias[sel][col], b1 = bias[sel][col + 1];
            float v00 = c[sel][nt][0] + b0, v01 = c[sel][nt][1] + b1;
            float v10 = c[sel][nt][2] + b0, v11 = c[sel][nt][3] + b1;
            u32 h0 = cvt2(v00, v01), l0 = cvt2(v00 - bflo(h0), v01 - bfhi(h0));
            u32 h1 = cvt2(v10, v11), l1 = cvt2(v10 - bflo(h1), v11 - bfhi(h1));
            *(u32*)&outh[sel][r0 * DHEAD + col] = h0;
            *(u32*)&outl[sel][r0 * DHEAD + col] = l0;
            *(u32*)&outh[sel][r1 * DHEAD + col] = h1;
            *(u32*)&outl[sel][r1 * DHEAD + col] = l1;
        }
    }
}

// ---------------------------------------------------------------------------
// Flash attention — EXACT round-8 code (best measured: 246.3us total).
// Paired q-tiles {31-bx, bx}, double-buffered cp.async K/V + drop_mask.
// ---------------------------------------------------------------------------
#define AS_STR 136
#define AS_ELE (64 * AS_STR)
#define DM_STR 68
#define KV_STG (4 * AS_ELE * 2)
#define DM_STG (64 * DM_STR * 4)
#define ATT_SMEM (2 * AS_ELE * 2 + 2 * KV_STG + 2 * DM_STG)   // 208896 B

__global__ __launch_bounds__(128) void attn_mma_kernel(
    const float* __restrict__ dm, float* __restrict__ out)
{
    extern __shared__ __align__(16) u16 sm_[];
    u16* Qh_s = sm_;
    u16* Ql_s = Qh_s + AS_ELE;
    const u32 smem_b = s2u(sm_);
    const u32 qh_b = smem_b;
    const u32 ql_b = qh_b + AS_ELE * 2;
    const u32 kv_b = ql_b + AS_ELE * 2;
    const u32 OFF_KL = AS_ELE * 2;
    const u32 OFF_VH = 2 * AS_ELE * 2;
    const u32 OFF_VL = 3 * AS_ELE * 2;
    const u32 dm_b = kv_b + 2 * KV_STG;
    float* dmS = (float*)(sm_ + 2 * AS_ELE + 4 * 2 * AS_ELE);

    const int tid = threadIdx.x, lane = tid & 31, wid = tid >> 5;
    const int b = blockIdx.y;
    const size_t brow = (size_t)b * SEQ;

    const u32 a_off = (u32)(wid * 16 + (lane & 15)) * (AS_STR * 2) +
                      ((lane & 16) ? 16u : 0u);
    const u32 bk_off = (u32)((lane & 7) + ((lane & 16) ? 8 : 0)) * (AS_STR * 2) +
                       ((lane & 8) ? 16u : 0u);
    const u32 bv_off = (u32)((lane & 7) + ((lane & 8) ? 8 : 0)) * (AS_STR * 2) +
                       ((lane & 16) ? 16u : 0u);

    const int sr = tid >> 4;
    const int scu = (tid & 15) * 8;
    const int dmc = (tid & 15) * 4;

    for (int half = 0; half < 2; half++) {
        const int qt = half == 0 ? (31 - (int)blockIdx.x) : (int)blockIdx.x;
        const int q0 = qt * 64;

        __syncthreads();
        #pragma unroll
        for (int l2 = 0; l2 < 8; l2++) {
            int r = sr + l2 * 8;
            size_t g = (brow + q0 + r) * DHEAD + scu;
            *(uint4*)&Qh_s[r * AS_STR + scu] = *(const uint4*)&g_Qh[g];
            *(uint4*)&Ql_s[r * AS_STR + scu] = *(const uint4*)&g_Ql[g];
        }
        {
            const u32 st = kv_b;
            #pragma unroll
            for (int l2 = 0; l2 < 8; l2++) {
                int r = sr + l2 * 8;
                size_t g = (brow + 0 + r) * DHEAD + scu;
                u32 so = (u32)(r * AS_STR + scu) * 2;
                cp16(st + so,          g_Kh + g);
                cp16(st + OFF_KL + so, g_Kl + g);
                cp16(st + OFF_VH + so, g_Vh + g);
                cp16(st + OFF_VL + so, g_Vl + g);
            }
            #pragma unroll
            for (int l2 = 0; l2 < 8; l2++) {
                int r = sr + l2 * 8;
                cp16(dm_b + (u32)(r * DM_STR + dmc) * 4,
                     &dm[(brow + q0 + r) * SEQ + 0 + dmc]);
            }
            CP_COMMIT();
        }

        float o[16][4];
        #pragma unroll
        for (int i = 0; i < 16; i++)
            #pragma unroll
            for (int j = 0; j < 4; j++) o[i][j] = 0.f;
        float m0 = -INFINITY, m1 = -INFINITY, l0 = 0.f, l1 = 0.f;

        const int rA = q0 + wid * 16 + (lane >> 2);
        const int rB = rA + 8;
        const int rloc = wid * 16 + (lane >> 2);

        for (int kt = 0; kt <= qt; kt++) {
            const int cur = kt & 1;
            CP_WAIT0();
            __syncthreads();

            if (kt < qt) {
                const int k1 = (kt + 1) * 64;
                const u32 st = kv_b + (u32)(cur ^ 1) * KV_STG;
                #pragma unroll
                for (int l2 = 0; l2 < 8; l2++) {
                    int r = sr + l2 * 8;
                    size_t g = (brow + k1 + r) * DHEAD + scu;
                    u32 so = (u32)(r * AS_STR + scu) * 2;
                    cp16(st + so,          g_Kh + g);
                    cp16(st + OFF_KL + so, g_Kl + g);
                    cp16(st + OFF_VH + so, g_Vh + g);
                    cp16(st + OFF_VL + so, g_Vl + g);
                }
                const u32 dst = dm_b + (u32)(cur ^ 1) * DM_STG;
                #pragma unroll
                for (int l2 = 0; l2 < 8; l2++) {
                    int r = sr + l2 * 8;
                    cp16(dst + (u32)(r * DM_STR + dmc) * 4,
                         &dm[(brow + q0 + r) * SEQ + k1 + dmc]);
                }
                CP_COMMIT();
            }

            const int k0 = kt * 64;
            const u32 kh_b = kv_b + (u32)cur * KV_STG;
            const u32 kl_b = kh_b + OFF_KL;
            const u32 vh_b = kh_b + OFF_VH;
            const u32 vl_b = kh_b + OFF_VL;
            const float* dmc_s = dmS + cur * (64 * DM_STR);

            float s[8][4];
            #pragma unroll
            for (int i = 0; i < 8; i++)
                #pragma unroll
                for (int j = 0; j < 4; j++) s[i][j] = 0.f;

            #pragma unroll
            for (int kc = 0; kc < 8; kc++) {
                u32 ah0, ah1, ah2, ah3, al0, al1, al2, al3;
                ldm_x4(ah0, ah1, ah2, ah3, qh_b + a_off + kc * 32);
                ldm_x4(al0, al1, al2, al3, ql_b + a_off + kc * 32);
                #pragma unroll
                for (int ntp = 0; ntp < 4; ntp++) {
                    u32 bh0, bh1, bh2, bh3, bl0, bl1, bl2, bl3;
                    u32 off = bk_off + (u32)(ntp * 16) * (AS_STR * 2) + kc * 32;
                    ldm_x4(bh0, bh1, bh2, bh3, kh_b + off);
                    ldm_x4(bl0, bl1, bl2, bl3, kl_b + off);
                    mma16816(s[2 * ntp], ah0, ah1, ah2, ah3, bh0, bh1);
                    mma16816(s[2 * ntp], ah0, ah1, ah2, ah3, bl0, bl1);
                    mma16816(s[2 * ntp], al0, al1, al2, al3, bh0, bh1);
                    mma16816(s[2 * ntp + 1], ah0, ah1, ah2, ah3, bh2, bh3);
                    mma16816(s[2 * ntp + 1], ah0, ah1, ah2, ah3, bl2, bl3);
                    mma16816(s[2 * ntp + 1], al0, al1, al2, al3, bh2, bh3);
                }
            }

            float mx0 = -INFINITY, mx1 = -INFINITY;
            #pragma unroll
            for (int nt = 0; nt < 8; nt++) {
                int kc0 = k0 + nt * 8 + (lane & 3) * 2;
                if (kc0     > rA || s[nt][0] == 0.f) s[nt][0] = -INFINITY;
                if (kc0 + 1 > rA || s[nt][1] == 0.f) s[nt][1] = -INFINITY;
                if (kc0     > rB || s[nt][2] == 0.f) s[nt][2] = -INFINITY;
                if (kc0 + 1 > rB || s[nt][3] == 0.f) s[nt][3] = -INFINITY;
                mx0 = fmaxf(mx0, fmaxf(s[nt][0], s[nt][1]));
                mx1 = fmaxf(mx1, fmaxf(s[nt][2], s[nt][3]));
            }
            mx0 = fmaxf(mx0, __shfl_xor_sync(0xffffffffu, mx0, 1));
            mx0 = fmaxf(mx0, __shfl_xor_sync(0xffffffffu, mx0, 2));
            mx1 = fmaxf(mx1, __shfl_xor_sync(0xffffffffu, mx1, 1));
            mx1 = fmaxf(mx1, __shfl_xor_sync(0xffffffffu, mx1, 2));

            float mn0 = fmaxf(m0, mx0), mn1 = fmaxf(m1, mx1);
            float sum0 = 0.f, sum1 = 0.f;
            #pragma unroll
            for (int nt = 0; nt < 8; nt++) {
                s[nt][0] = __expf(s[nt][0] - mn0);
                s[nt][1] = __expf(s[nt][1] - mn0);
                s[nt][2] = __expf(s[nt][2] - mn1);
                s[nt][3] = __expf(s[nt][3] - mn1);
                sum0 += s[nt][0] + s[nt][1];
                sum1 += s[nt][2] + s[nt][3];
            }
            sum0 += __shfl_xor_sync(0xffffffffu, sum0, 1);
            sum0 += __shfl_xor_sync(0xffffffffu, sum0, 2);
            sum1 += __shfl_xor_sync(0xffffffffu, sum1, 1);
            sum1 += __shfl_xor_sync(0xffffffffu, sum1, 2);

            float sc0 = __expf(m0 - mn0), sc1 = __expf(m1 - mn1);
            l0 = l0 * sc0 + sum0;  m0 = mn0;
            l1 = l1 * sc1 + sum1;  m1 = mn1;

            #pragma unroll
            for (int nt = 0; nt < 16; nt++) {
                o[nt][0] *= sc0; o[nt][1] *= sc0;
                o[nt][2] *= sc1; o[nt][3] *= sc1;
            }

            #pragma unroll
            for (int nt = 0; nt < 8; nt++) {
                int kcl = nt * 8 + (lane & 3) * 2;
                float2 ma = *(const float2*)&dmc_s[rloc * DM_STR + kcl];
                float2 mb = *(const float2*)&dmc_s[(rloc + 8) * DM_STR + kcl];
                s[nt][0] *= ma.x; s[nt][1] *= ma.y;
                s[nt][2] *= mb.x; s[nt][3] *= mb.y;
            }

            #pragma unroll
            for (int tc = 0; tc < 4; tc++) {
                u32 ph0 = cvt2(s[2 * tc][0], s[2 * tc][1]);
                u32 pl0 = cvt2(s[2 * tc][0] - bflo(ph0), s[2 * tc][1] - bfhi(ph0));
                u32 ph1 = cvt2(s[2 * tc][2], s[2 * tc][3]);
                u32 pl1 = cvt2(s[2 * tc][2] - bflo(ph1), s[2 * tc][3] - bfhi(ph1));
                u32 ph2 = cvt2(s[2 * tc + 1][0], s[2 * tc + 1][1]);
                u32 pl2 = cvt2(s[2 * tc + 1][0] - bflo(ph2), s[2 * tc + 1][1] - bfhi(ph2));
                u32 ph3 = cvt2(s[2 * tc + 1][2], s[2 * tc + 1][3]);
                u32 pl3 = cvt2(s[2 * tc + 1][2] - bflo(ph3), s[2 * tc + 1][3] - bfhi(ph3));
                #pragma unroll
                for (int ntp = 0; ntp < 8; ntp++) {
                    u32 bh0, bh1, bh2, bh3, bl0, bl1, bl2, bl3;
                    u32 off = bv_off + (u32)(tc * 16) * (AS_STR * 2) + ntp * 32;
                    ldm_x4t(bh0, bh1, bh2, bh3, vh_b + off);
                    ldm_x4t(bl0, bl1, bl2, bl3, vl_b + off);
                    mma16816(o[2 * ntp], ph0, ph1, ph2, ph3, bh0, bh1);
                    mma16816(o[2 * ntp], ph0, ph1, ph2, ph3, bl0, bl1);
                    mma16816(o[2 * ntp], pl0, pl1, pl2, pl3, bh0, bh1);
                    mma16816(o[2 * ntp + 1], ph0, ph1, ph2, ph3, bh2, bh3);
                    mma16816(o[2 * ntp + 1], ph0, ph1, ph2, ph3, bl2, bl3);
                    mma16816(o[2 * ntp + 1], pl0, pl1, pl2, pl3, bh2, bh3);
                }
            }
        } // kt

        float inv0 = 1.0f / l0, inv1 = 1.0f / l1;
        #pragma unroll
        for (int nt = 0; nt < 16; nt++) {
            int col = nt * 8 + (lane & 3) * 2;
            float2 v0 = make_float2(o[nt][0] * inv0, o[nt][1] * inv0);
            float2 v1 = make_float2(o[nt][2] * inv1, o[nt][3] * inv1);
            *(float2*)&out[(brow + rA) * DHEAD + col] = v0;
            *(float2*)&out[(brow + rB) * DHEAD + col] = v1;
        }
    } // half
}

// ---------------------------------------------------------------------------
extern "C" void kernel_launch(void* const* d_in, const int* in_sizes, int n_in,
                              void* d_out, int out_size)
{
    const float* X  = (const float*)d_in[0];
    const float* Wq = (const float*)d_in[1];
    const float* bq = (const float*)d_in[2];
    const float* Wk = (const float*)d_in[3];
    const float* bk = (const float*)d_in[4];
    const float* Wv = (const float*)d_in[5];
    const float* bv = (const float*)d_in[6];
    const float* dm = (const float*)d_in[7];
    float* out = (float*)d_out;

    split_w_kernel<<<384, 256>>>(Wq, Wk, Wv);

    cudaFuncSetAttribute(proj_mma_kernel,
                         cudaFuncAttributeMaxDynamicSharedMemorySize, PROJ_SMEM);
    proj_mma_kernel<<<NROWS / 64, 128, PROJ_SMEM>>>(X, bq, bk, bv);

    cudaFuncSetAttribute(attn_mma_kernel,
                         cudaFuncAttributeMaxDynamicSharedMemorySize, ATT_SMEM);
    dim3 ga(16, BATCH);
    attn_mma_kernel<<<ga, 128, ATT_SMEM>>>(dm, out);
}